// round 13
// baseline (speedup 1.0000x reference)
#include <cuda_runtime.h>
#include <cuda_fp16.h>
#include <cstdint>

// ---------------- problem constants ----------------
constexpr int B = 2;
constexpr int D = 64;
constexpr int N = 96 * 96;      // 9216
constexpr int ITERS = 4;
constexpr float STEP = 0.5f;
constexpr float KBW = 0.3f;
constexpr float LOG2E = 1.4426950408889634f;

constexpr int BM = 128;
constexpr int BN = 128;
constexpr int THREADS = 512;
constexpr int NT = N / BN;      // 72
constexpr int STAGES = 8;

// Tile image: 2 chunks x [64 d][64 pt] fp16, 128B swizzled rows = 16384 B
constexpr int IMG = 16384;

// ping-pong operand buffers (iter parity)
__device__ __align__(16) unsigned char g_xh[2][(size_t)B * NT * IMG];
__device__ float g_tsh[2][(size_t)B * N];

// ---------------- smem layout (bytes) ----------------
constexpr int XM_H = 0;              // 16 KB
constexpr int XN_BASE = 16384;       // STAGES x 16 KB
constexpr int XN_STRIDE = 16384;
constexpr int SDEN = XN_BASE + STAGES * XN_STRIDE;   // 147456; 256 f32
constexpr int MBAR = SDEN + 1024;
constexpr int SMEM_BYTES = MBAR + 256;
// epilogue reuse: sO0 f32[64][132] at 0, sO1 at 33792; then sP f32[16][128] at 0

// ---------------- asm helpers ----------------
__device__ __forceinline__ uint32_t smem_u32(const void* p) {
    uint32_t a;
    asm("{ .reg .u64 t; cvta.to.shared.u64 t, %1; cvt.u32.u64 %0, t; }"
        : "=r"(a) : "l"(p));
    return a;
}

__device__ __forceinline__ uint32_t swz(uint32_t o) {
    return o ^ ((o >> 3) & 0x70);
}

#define MBAR_INIT(mbar, cnt) \
    asm volatile("mbarrier.init.shared.b64 [%0], %1;" :: "r"(mbar), "r"(cnt) : "memory")

#define MBAR_EXPECT_TX(mbar, bytes) \
    asm volatile("mbarrier.arrive.expect_tx.shared.b64 _, [%0], %1;" \
                 :: "r"(mbar), "r"(bytes) : "memory")

#define MBAR_ARRIVE(mbar) \
    asm volatile("mbarrier.arrive.shared.b64 _, [%0];" :: "r"(mbar) : "memory")

#define MBAR_WAIT(mbar, parity) do {                                          \
    uint32_t _m = (mbar), _p = (parity);                                      \
    asm volatile(                                                             \
        "{\n\t.reg .pred P1;\n\t"                                             \
        "WAIT_LOOP_%=:\n\t"                                                   \
        "mbarrier.try_wait.parity.acquire.cta.shared::cta.b64 P1, [%0], %1, 0x989680;\n\t" \
        "@P1 bra.uni WAIT_DONE_%=;\n\t"                                       \
        "bra.uni WAIT_LOOP_%=;\n\t"                                           \
        "WAIT_DONE_%=:\n\t}"                                                  \
        :: "r"(_m), "r"(_p) : "memory");                                      \
} while (0)

__device__ __forceinline__ void bulk_g2s(uint32_t dst, const void* src,
                                         uint32_t bytes, uint32_t mbar) {
    asm volatile(
        "cp.async.bulk.shared::cluster.global.mbarrier::complete_tx::bytes "
        "[%0], [%1], %2, [%3];"
        :: "r"(dst), "l"(__cvta_generic_to_global(src)), "r"(bytes), "r"(mbar)
        : "memory");
}

#define LDSM_X4(r, addr)                                                     \
    asm volatile("ldmatrix.sync.aligned.m8n8.x4.shared.b16 {%0,%1,%2,%3}, [%4];" \
        : "=r"((r)[0]), "=r"((r)[1]), "=r"((r)[2]), "=r"((r)[3]) : "r"(addr))

#define LDSM_X4_T(r, addr)                                                   \
    asm volatile("ldmatrix.sync.aligned.m8n8.x4.trans.shared.b16 {%0,%1,%2,%3}, [%4];" \
        : "=r"((r)[0]), "=r"((r)[1]), "=r"((r)[2]), "=r"((r)[3]) : "r"(addr))

__device__ __forceinline__ void hmma(float* c, const uint32_t* a, const uint32_t* b) {
    asm volatile(
        "mma.sync.aligned.m16n8k16.row.col.f32.f16.f16.f32 "
        "{%0,%1,%2,%3}, {%4,%5,%6,%7}, {%8,%9}, {%0,%1,%2,%3};"
        : "+f"(c[0]), "+f"(c[1]), "+f"(c[2]), "+f"(c[3])
        : "r"(a[0]), "r"(a[1]), "r"(a[2]), "r"(a[3]), "r"(b[0]), "r"(b[1]));
}

// pack two f32 into f16x2 (lo = second arg), saturating to finite
__device__ __forceinline__ uint32_t pack_f16(float hi, float lo) {
    uint32_t r;
    asm("cvt.rn.satfinite.f16x2.f32 %0, %1, %2;" : "=r"(r) : "f"(hi), "f"(lo));
    return r;
}

// 2^t via MUFU (otherwise-idle pipe; ~2 ulp)
__device__ __forceinline__ float ex2a(float t) {
    float r;
    asm("ex2.approx.f32 %0, %1;" : "=f"(r) : "f"(t));
    return r;
}

// init: copy x0 into out slice 0, build fp16 image buf0 + tsh buf0
__global__ __launch_bounds__(256)
void init_kernel(const float* __restrict__ x, float* __restrict__ out) {
    const int t = blockIdx.x, b = blockIdx.y;
    const int tid = threadIdx.x;
    const float* xs = x + (size_t)b * D * N;
    float* os = out + (size_t)b * (ITERS + 1) * D * N;
    unsigned char* ph = g_xh[0] + (size_t)(b * NT + t) * IMG;
    #pragma unroll
    for (int q = 0; q < 4; ++q) {
        int task = q * 256 + tid;          // c(2) x d(64) x g(8)
        int c = task >> 9, rem = task & 511;
        int d = rem >> 3, g = rem & 7;
        int n0 = t * BN + c * 64 + g * 8;
        const float4* s = (const float4*)(xs + (size_t)d * N + n0);
        float4 v0 = s[0], v1 = s[1];
        float4* o = (float4*)(os + (size_t)d * N + n0);
        o[0] = v0;
        o[1] = v1;
        uint32_t hp[4];
        hp[0] = pack_f16(v0.y, v0.x);
        hp[1] = pack_f16(v0.w, v0.z);
        hp[2] = pack_f16(v1.y, v1.x);
        hp[3] = pack_f16(v1.w, v1.z);
        uint32_t off = c * 8192 + swz((uint32_t)(d * 128 + g * 16));
        *(uint4*)(ph + off) = make_uint4(hp[0], hp[1], hp[2], hp[3]);
    }
    if (tid < BN) {
        int n = t * BN + tid;
        float s = 0.0f;
        #pragma unroll 8
        for (int d = 0; d < D; ++d) {
            float v = xs[(size_t)d * N + n];
            s = fmaf(v, v, s);
        }
        g_tsh[0][(size_t)b * N + n] = fmaf(KBW * LOG2E, s, 2.0f);
    }
}

// ---------------- main kernel ----------------
__global__ __launch_bounds__(THREADS, 1)
void ms_mma_kernel(float* __restrict__ out, int it) {
    extern __shared__ unsigned char smc[];
    uint32_t sb = smem_u32(smc);

    const int tid = threadIdx.x;
    const int l = tid & 31;
    const int w = tid >> 5;
    const int wm = w >> 1;       // 8 m-groups of 16 rows
    const int wn = w & 1;        // 2 n-groups of 64 cols

    const int b = blockIdx.y;
    const int m0 = blockIdx.x * BM;
    const float* __restrict__ xin = out + ((size_t)b * (ITERS + 1) + it) * (size_t)(D * N);
    float* __restrict__ xout = (float*)xin + (size_t)D * N;

    const int l7 = l & 7, l8 = l & 8, l16h = (l & 16) >> 1, lq = l >> 2, lr = l & 3;

    const uint32_t mbF = sb + MBAR;            // full[8]
    const uint32_t mbE = sb + MBAR + 64;       // empty[8]
    const uint32_t mbx = sb + MBAR + 128;

    // ---- prologue ----
    if (tid == 0) {
        #pragma unroll
        for (int s = 0; s < STAGES; ++s) {
            MBAR_INIT(mbF + s * 8, 1);
            MBAR_INIT(mbE + s * 8, 16);
        }
        MBAR_INIT(mbx, 1);
    }
    __syncthreads();
    const unsigned char* gh = g_xh[it & 1] + (size_t)b * NT * IMG;
    if (tid == 0) {
        MBAR_EXPECT_TX(mbx, IMG);
        bulk_g2s(sb + XM_H, gh + (size_t)blockIdx.x * IMG, IMG, mbx);
        #pragma unroll
        for (int u = 0; u < 6; ++u) {
            MBAR_EXPECT_TX(mbF + u * 8, IMG);
            bulk_g2s(sb + XN_BASE + u * XN_STRIDE, gh + (size_t)u * IMG, IMG, mbF + u * 8);
        }
    }

    // per-warp address components
    const int mchunk = (wm >> 2) * 8192;
    const int mcol = (wm & 3) * 16 + l8;
    const int nchunk = wn * 8192;

    // per-thread K-column shifts (rows mA, mA+8)
    const int mA = wm * 16 + lq;
    const float ntsA = -g_tsh[it & 1][(size_t)b * N + m0 + mA];
    const float ntsB = -g_tsh[it & 1][(size_t)b * N + m0 + mA + 8];
    const float C = KBW * LOG2E;

    float accO[8][4];
    #pragma unroll
    for (int j = 0; j < 8; ++j)
        #pragma unroll
        for (int c = 0; c < 4; ++c) accO[j][c] = 0.0f;
    float dsum0 = 0.0f, dsum1 = 0.0f;

    // ---- hoist Xmh A-fragments (loop-invariant, 16 regs) ----
    MBAR_WAIT(mbx, 0);
    uint32_t Ah[4][4];
    #pragma unroll
    for (int k = 0; k < 4; ++k) {
        const uint32_t offA =
            swz((uint32_t)((k * 16 + l7 + l16h) * 128 + mcol * 2)) + mchunk;
        LDSM_X4_T(Ah[k], sb + XM_H + offA);
    }

    for (int t = 0; t < NT; ++t) {
        // producer: prefetch tile t+6 into stage (t+6)%STAGES
        if (tid == 0) {
            const int u = t + 6;
            if (u < NT) {
                const int us = u & 7, uj = u >> 3;
                if (u >= STAGES) MBAR_WAIT(mbE + us * 8, (uj - 1) & 1);
                MBAR_EXPECT_TX(mbF + us * 8, IMG);
                bulk_g2s(sb + XN_BASE + us * XN_STRIDE, gh + (size_t)u * IMG,
                         IMG, mbF + us * 8);
            }
        }
        const int cs = t & 7;
        const uint32_t XNB = sb + XN_BASE + cs * XN_STRIDE;
        MBAR_WAIT(mbF + cs * 8, (t >> 3) & 1);

        // ---- fused per n-group: S-slice -> (B2 preload) -> exp -> O-slice ----
        #pragma unroll
        for (int np = 0; np < 4; ++np) {
            // MMA1 B fragments (4 k-steps batched)
            uint32_t Bh[16];
            #pragma unroll
            for (int k = 0; k < 4; ++k) {
                const uint32_t offB =
                    swz((uint32_t)((k * 16 + l7 + l8) * 128 + (np * 16 + l16h) * 2))
                    + nchunk;
                LDSM_X4_T(Bh + 4 * k, XNB + offB);
            }
            float s0[4] = {0.0f, 0.0f, 0.0f, 0.0f};
            float s1[4] = {0.0f, 0.0f, 0.0f, 0.0f};
            #pragma unroll
            for (int k = 0; k < 4; ++k) {
                hmma(s0, Ah[k], Bh + 4 * k);
                hmma(s1, Ah[k], Bh + 4 * k + 2);
            }
            // MMA2 B fragments preloaded BEFORE the exp chain (latency overlap)
            uint32_t B2[16];
            const int kcol = np * 16 + l8;
            #pragma unroll
            for (int dg = 0; dg < 4; ++dg) {
                const int dd = dg * 16 + l7 + l16h;
                const uint32_t off =
                    swz((uint32_t)(dd * 128 + kcol * 2)) + nchunk;
                LDSM_X4(B2 + 4 * dg, XNB + off);
            }
            // K' = 2^(C*S - tsh) via MUFU -> fp16 A fragment; den in f32
            float e0 = ex2a(fmaf(s0[0], C, ntsA));
            float e1 = ex2a(fmaf(s0[1], C, ntsA));
            float e2 = ex2a(fmaf(s0[2], C, ntsB));
            float e3 = ex2a(fmaf(s0[3], C, ntsB));
            float f0 = ex2a(fmaf(s1[0], C, ntsA));
            float f1 = ex2a(fmaf(s1[1], C, ntsA));
            float f2 = ex2a(fmaf(s1[2], C, ntsB));
            float f3 = ex2a(fmaf(s1[3], C, ntsB));
            dsum0 += (e0 + e1) + (f0 + f1);
            dsum1 += (e2 + e3) + (f2 + f3);
            uint32_t AK[4];
            AK[0] = pack_f16(e1, e0);
            AK[1] = pack_f16(e3, e2);
            AK[2] = pack_f16(f1, f0);
            AK[3] = pack_f16(f3, f2);
            #pragma unroll
            for (int dg = 0; dg < 4; ++dg) {
                hmma(accO[2 * dg],     AK, B2 + 4 * dg);
                hmma(accO[2 * dg + 1], AK, B2 + 4 * dg + 2);
            }
        }

        // done reading stage cs
        if (l == 0) MBAR_ARRIVE(mbE + cs * 8);
    }

    // ---- den reduction: shfl across quad lanes, write per n-group ----
    float* sDen = (float*)(smc + SDEN);     // [2][128]
    {
        float v0 = dsum0, v1 = dsum1;
        v0 += __shfl_xor_sync(0xFFFFFFFFu, v0, 1);
        v0 += __shfl_xor_sync(0xFFFFFFFFu, v0, 2);
        v1 += __shfl_xor_sync(0xFFFFFFFFu, v1, 1);
        v1 += __shfl_xor_sync(0xFFFFFFFFu, v1, 2);
        if (lr == 0) {
            sDen[wn * 128 + mA] = v0;
            sDen[wn * 128 + mA + 8] = v1;
        }
    }
    __syncthreads();   // all warps done with all tiles; sDen visible

    // ---- partial-O epilogue: scale by STEP/den, write per n-group region ----
    const int mB2 = mA + 8;
    const float scA = STEP / (sDen[mA] + sDen[128 + mA]);
    const float scB = STEP / (sDen[mB2] + sDen[128 + mB2]);
    float* sO = (float*)(smc + wn * 33792);   // [64 d][132 m]
    #pragma unroll
    for (int dg = 0; dg < 4; ++dg)
        #pragma unroll
        for (int s = 0; s < 2; ++s) {
            const float* c = accO[2 * dg + s];
            const int dbase = dg * 16 + s * 8 + 2 * lr;
            sO[dbase * 132 + mA]        = c[0] * scA;
            sO[(dbase + 1) * 132 + mA]  = c[1] * scA;
            sO[dbase * 132 + mB2]       = c[2] * scB;
            sO[(dbase + 1) * 132 + mB2] = c[3] * scB;
        }
    __syncthreads();

    // ---- combine partials + blend with x, store + next-iter image ----
    unsigned char* phn = g_xh[(it + 1) & 1] + (size_t)(b * NT + blockIdx.x) * IMG;
    const float* sO0 = (const float*)(smc);
    const float* sO1 = (const float*)(smc + 33792);
    float psum[4] = {0.0f, 0.0f, 0.0f, 0.0f};
    #pragma unroll
    for (int q = 0; q < 4; ++q) {
        int task = q * THREADS + tid;       // dd(64) x mq(32)
        int dd = task >> 5, mq = task & 31;
        float4 o0 = *(const float4*)&sO0[dd * 132 + mq * 4];
        float4 o1 = *(const float4*)&sO1[dd * 132 + mq * 4];
        float4 x = *(const float4*)(xin + (size_t)dd * N + m0 + mq * 4);
        float4 r;
        r.x = fmaf(1.0f - STEP, x.x, o0.x + o1.x);
        r.y = fmaf(1.0f - STEP, x.y, o0.y + o1.y);
        r.z = fmaf(1.0f - STEP, x.z, o0.z + o1.z);
        r.w = fmaf(1.0f - STEP, x.w, o0.w + o1.w);
        *(float4*)(xout + (size_t)dd * N + m0 + mq * 4) = r;
        // next-iteration fp16 image (ping-pong buffer)
        uint32_t hp0 = pack_f16(r.y, r.x);
        uint32_t hp1 = pack_f16(r.w, r.z);
        int mit = mq * 4;
        uint32_t off = (mit >> 6) * 8192
                     + swz((uint32_t)(dd * 128 + ((mit & 63) >> 3) * 16))
                     + (mit & 7) * 2;
        *(uint2*)(phn + off) = make_uint2(hp0, hp1);
        psum[0] = fmaf(r.x, r.x, psum[0]);
        psum[1] = fmaf(r.y, r.y, psum[1]);
        psum[2] = fmaf(r.z, r.z, psum[2]);
        psum[3] = fmaf(r.w, r.w, psum[3]);
    }
    __syncthreads();   // sO reads done; reuse region for norm reduction
    float* sP = (float*)smc;               // [16][128]
    {
        int grp = tid >> 5, mq = tid & 31;
        #pragma unroll
        for (int j = 0; j < 4; ++j)
            sP[grp * 128 + mq * 4 + j] = psum[j];
    }
    __syncthreads();
    if (tid < BM) {
        float s = 0.0f;
        #pragma unroll
        for (int g = 0; g < 16; ++g) s += sP[g * 128 + tid];
        g_tsh[(it + 1) & 1][(size_t)b * N + m0 + tid] = fmaf(C, s, 2.0f);
    }
}

extern "C" void kernel_launch(void* const* d_in, const int* in_sizes, int n_in,
                              void* d_out, int out_size) {
    const float* x = (const float*)d_in[0];
    float* out = (float*)d_out;

    cudaFuncSetAttribute(ms_mma_kernel,
                         cudaFuncAttributeMaxDynamicSharedMemorySize, SMEM_BYTES);

    dim3 grid(NT, B);
    init_kernel<<<grid, 256>>>(x, out);
    for (int it = 0; it < ITERS; ++it)
        ms_mma_kernel<<<grid, THREADS, SMEM_BYTES>>>(out, it);
}

// round 14
// speedup vs baseline: 1.0176x; 1.0176x over previous
#include <cuda_runtime.h>
#include <cuda_fp16.h>
#include <cstdint>

// ---------------- problem constants ----------------
constexpr int B = 2;
constexpr int D = 64;
constexpr int N = 96 * 96;      // 9216
constexpr int ITERS = 4;
constexpr float STEP = 0.5f;
constexpr float KBW = 0.3f;
constexpr float LOG2E = 1.4426950408889634f;

constexpr int BM = 128;
constexpr int BN = 128;
constexpr int THREADS = 512;
constexpr int NT = N / BN;      // 72
constexpr int STAGES = 8;

// Tile image: 2 chunks x [64 d][64 pt] fp16, 128B swizzled rows = 16384 B
constexpr int IMG = 16384;

// ping-pong operand buffers (iter parity)
__device__ __align__(16) unsigned char g_xh[2][(size_t)B * NT * IMG];
__device__ float g_tsh[2][(size_t)B * N];

// ---------------- smem layout (bytes) ----------------
constexpr int XM_H = 0;              // 16 KB
constexpr int XN_BASE = 16384;       // STAGES x 16 KB
constexpr int XN_STRIDE = 16384;
constexpr int SDEN = XN_BASE + STAGES * XN_STRIDE;   // 147456; 256 f32
constexpr int MBAR = SDEN + 1024;
constexpr int SMEM_BYTES = MBAR + 256;
// epilogue reuse: sO0 f32[64][132] at 0, sO1 at 33792; then sP f32[16][128] at 0

// ---------------- asm helpers ----------------
__device__ __forceinline__ uint32_t smem_u32(const void* p) {
    uint32_t a;
    asm("{ .reg .u64 t; cvta.to.shared.u64 t, %1; cvt.u32.u64 %0, t; }"
        : "=r"(a) : "l"(p));
    return a;
}

__device__ __forceinline__ uint32_t swz(uint32_t o) {
    return o ^ ((o >> 3) & 0x70);
}

#define MBAR_INIT(mbar, cnt) \
    asm volatile("mbarrier.init.shared.b64 [%0], %1;" :: "r"(mbar), "r"(cnt) : "memory")

#define MBAR_EXPECT_TX(mbar, bytes) \
    asm volatile("mbarrier.arrive.expect_tx.shared.b64 _, [%0], %1;" \
                 :: "r"(mbar), "r"(bytes) : "memory")

#define MBAR_ARRIVE(mbar) \
    asm volatile("mbarrier.arrive.shared.b64 _, [%0];" :: "r"(mbar) : "memory")

#define MBAR_WAIT(mbar, parity) do {                                          \
    uint32_t _m = (mbar), _p = (parity);                                      \
    asm volatile(                                                             \
        "{\n\t.reg .pred P1;\n\t"                                             \
        "WAIT_LOOP_%=:\n\t"                                                   \
        "mbarrier.try_wait.parity.acquire.cta.shared::cta.b64 P1, [%0], %1, 0x989680;\n\t" \
        "@P1 bra.uni WAIT_DONE_%=;\n\t"                                       \
        "bra.uni WAIT_LOOP_%=;\n\t"                                           \
        "WAIT_DONE_%=:\n\t}"                                                  \
        :: "r"(_m), "r"(_p) : "memory");                                      \
} while (0)

__device__ __forceinline__ void bulk_g2s(uint32_t dst, const void* src,
                                         uint32_t bytes, uint32_t mbar) {
    asm volatile(
        "cp.async.bulk.shared::cluster.global.mbarrier::complete_tx::bytes "
        "[%0], [%1], %2, [%3];"
        :: "r"(dst), "l"(__cvta_generic_to_global(src)), "r"(bytes), "r"(mbar)
        : "memory");
}

#define LDSM_X4(r, addr)                                                     \
    asm volatile("ldmatrix.sync.aligned.m8n8.x4.shared.b16 {%0,%1,%2,%3}, [%4];" \
        : "=r"((r)[0]), "=r"((r)[1]), "=r"((r)[2]), "=r"((r)[3]) : "r"(addr))

#define LDSM_X4_T(r, addr)                                                   \
    asm volatile("ldmatrix.sync.aligned.m8n8.x4.trans.shared.b16 {%0,%1,%2,%3}, [%4];" \
        : "=r"((r)[0]), "=r"((r)[1]), "=r"((r)[2]), "=r"((r)[3]) : "r"(addr))

__device__ __forceinline__ void hmma(float* c, const uint32_t* a, const uint32_t* b) {
    asm volatile(
        "mma.sync.aligned.m16n8k16.row.col.f32.f16.f16.f32 "
        "{%0,%1,%2,%3}, {%4,%5,%6,%7}, {%8,%9}, {%0,%1,%2,%3};"
        : "+f"(c[0]), "+f"(c[1]), "+f"(c[2]), "+f"(c[3])
        : "r"(a[0]), "r"(a[1]), "r"(a[2]), "r"(a[3]), "r"(b[0]), "r"(b[1]));
}

// pack two f32 into f16x2 (lo = second arg), saturating to finite
__device__ __forceinline__ uint32_t pack_f16(float hi, float lo) {
    uint32_t r;
    asm("cvt.rn.satfinite.f16x2.f32 %0, %1, %2;" : "=r"(r) : "f"(hi), "f"(lo));
    return r;
}

// 2^t via MUFU (otherwise-idle pipe; ~2 ulp)
__device__ __forceinline__ float ex2a(float t) {
    float r;
    asm("ex2.approx.f32 %0, %1;" : "=f"(r) : "f"(t));
    return r;
}

// init: copy x0 into out slice 0, build fp16 image buf0 + tsh buf0
__global__ __launch_bounds__(256)
void init_kernel(const float* __restrict__ x, float* __restrict__ out) {
    const int t = blockIdx.x, b = blockIdx.y;
    const int tid = threadIdx.x;
    const float* xs = x + (size_t)b * D * N;
    float* os = out + (size_t)b * (ITERS + 1) * D * N;
    unsigned char* ph = g_xh[0] + (size_t)(b * NT + t) * IMG;
    #pragma unroll
    for (int q = 0; q < 4; ++q) {
        int task = q * 256 + tid;          // c(2) x d(64) x g(8)
        int c = task >> 9, rem = task & 511;
        int d = rem >> 3, g = rem & 7;
        int n0 = t * BN + c * 64 + g * 8;
        const float4* s = (const float4*)(xs + (size_t)d * N + n0);
        float4 v0 = s[0], v1 = s[1];
        float4* o = (float4*)(os + (size_t)d * N + n0);
        o[0] = v0;
        o[1] = v1;
        uint32_t hp[4];
        hp[0] = pack_f16(v0.y, v0.x);
        hp[1] = pack_f16(v0.w, v0.z);
        hp[2] = pack_f16(v1.y, v1.x);
        hp[3] = pack_f16(v1.w, v1.z);
        uint32_t off = c * 8192 + swz((uint32_t)(d * 128 + g * 16));
        *(uint4*)(ph + off) = make_uint4(hp[0], hp[1], hp[2], hp[3]);
    }
    if (tid < BN) {
        int n = t * BN + tid;
        float s = 0.0f;
        #pragma unroll 8
        for (int d = 0; d < D; ++d) {
            float v = xs[(size_t)d * N + n];
            s = fmaf(v, v, s);
        }
        g_tsh[0][(size_t)b * N + n] = fmaf(KBW * LOG2E, s, 2.0f);
    }
}

// ---------------- main kernel ----------------
__global__ __launch_bounds__(THREADS, 1)
void ms_mma_kernel(float* __restrict__ out, int it) {
    extern __shared__ unsigned char smc[];
    uint32_t sb = smem_u32(smc);

    const int tid = threadIdx.x;
    const int l = tid & 31;
    const int w = tid >> 5;
    const int wm = w >> 1;       // 8 m-groups of 16 rows
    const int wn = w & 1;        // 2 n-groups of 64 cols

    const int b = blockIdx.y;
    const int m0 = blockIdx.x * BM;
    const float* __restrict__ xin = out + ((size_t)b * (ITERS + 1) + it) * (size_t)(D * N);
    float* __restrict__ xout = (float*)xin + (size_t)D * N;

    const int l7 = l & 7, l8 = l & 8, l16h = (l & 16) >> 1, lq = l >> 2, lr = l & 3;

    const uint32_t mbF = sb + MBAR;            // full[8]
    const uint32_t mbE = sb + MBAR + 64;       // empty[8]
    const uint32_t mbx = sb + MBAR + 128;

    // ---- prologue ----
    if (tid == 0) {
        #pragma unroll
        for (int s = 0; s < STAGES; ++s) {
            MBAR_INIT(mbF + s * 8, 1);
            MBAR_INIT(mbE + s * 8, 16);
        }
        MBAR_INIT(mbx, 1);
    }
    __syncthreads();
    const unsigned char* gh = g_xh[it & 1] + (size_t)b * NT * IMG;
    if (tid == 0) {
        MBAR_EXPECT_TX(mbx, IMG);
        bulk_g2s(sb + XM_H, gh + (size_t)blockIdx.x * IMG, IMG, mbx);
        #pragma unroll
        for (int u = 0; u < 6; ++u) {
            MBAR_EXPECT_TX(mbF + u * 8, IMG);
            bulk_g2s(sb + XN_BASE + u * XN_STRIDE, gh + (size_t)u * IMG, IMG, mbF + u * 8);
        }
    }

    // per-warp address components
    const int mchunk = (wm >> 2) * 8192;
    const int mcol = (wm & 3) * 16 + l8;
    const int nchunk = wn * 8192;

    // per-thread K-column shifts (rows mA, mA+8)
    const int mA = wm * 16 + lq;
    const float ntsA = -g_tsh[it & 1][(size_t)b * N + m0 + mA];
    const float ntsB = -g_tsh[it & 1][(size_t)b * N + m0 + mA + 8];
    const float C = KBW * LOG2E;

    float accO[8][4];
    #pragma unroll
    for (int j = 0; j < 8; ++j)
        #pragma unroll
        for (int c = 0; c < 4; ++c) accO[j][c] = 0.0f;
    float dsum0 = 0.0f, dsum1 = 0.0f;

    // ---- hoist Xmh A-fragments (loop-invariant, 16 regs) ----
    MBAR_WAIT(mbx, 0);
    uint32_t Ah[4][4];
    #pragma unroll
    for (int k = 0; k < 4; ++k) {
        const uint32_t offA =
            swz((uint32_t)((k * 16 + l7 + l16h) * 128 + mcol * 2)) + mchunk;
        LDSM_X4_T(Ah[k], sb + XM_H + offA);
    }

    for (int t = 0; t < NT; ++t) {
        // producer: prefetch tile t+6 into stage (t+6)%STAGES
        if (tid == 0) {
            const int u = t + 6;
            if (u < NT) {
                const int us = u & 7, uj = u >> 3;
                if (u >= STAGES) MBAR_WAIT(mbE + us * 8, (uj - 1) & 1);
                MBAR_EXPECT_TX(mbF + us * 8, IMG);
                bulk_g2s(sb + XN_BASE + us * XN_STRIDE, gh + (size_t)u * IMG,
                         IMG, mbF + us * 8);
            }
        }
        const int cs = t & 7;
        const uint32_t XNB = sb + XN_BASE + cs * XN_STRIDE;
        MBAR_WAIT(mbF + cs * 8, (t >> 3) & 1);

        // ---- fused per n-group: S-slice -> exp -> O-slice ----
        #pragma unroll
        for (int np = 0; np < 4; ++np) {
            float s0[4] = {0.0f, 0.0f, 0.0f, 0.0f};
            float s1[4] = {0.0f, 0.0f, 0.0f, 0.0f};
            #pragma unroll
            for (int k = 0; k < 4; ++k) {
                uint32_t Bh[4];
                const uint32_t offB =
                    swz((uint32_t)((k * 16 + l7 + l8) * 128 + (np * 16 + l16h) * 2))
                    + nchunk;
                LDSM_X4_T(Bh, XNB + offB);
                hmma(s0, Ah[k], Bh);
                hmma(s1, Ah[k], Bh + 2);
            }
            // K' = 2^(C*S - tsh) via MUFU -> fp16 A fragment; den in f32
            float e0 = ex2a(fmaf(s0[0], C, ntsA));
            float e1 = ex2a(fmaf(s0[1], C, ntsA));
            float e2 = ex2a(fmaf(s0[2], C, ntsB));
            float e3 = ex2a(fmaf(s0[3], C, ntsB));
            float f0 = ex2a(fmaf(s1[0], C, ntsA));
            float f1 = ex2a(fmaf(s1[1], C, ntsA));
            float f2 = ex2a(fmaf(s1[2], C, ntsB));
            float f3 = ex2a(fmaf(s1[3], C, ntsB));
            dsum0 += (e0 + e1) + (f0 + f1);
            dsum1 += (e2 + e3) + (f2 + f3);
            uint32_t AK[4];
            AK[0] = pack_f16(e1, e0);
            AK[1] = pack_f16(e3, e2);
            AK[2] = pack_f16(f1, f0);
            AK[3] = pack_f16(f3, f2);
            const int kcol = np * 16 + l8;
            #pragma unroll
            for (int dg = 0; dg < 4; ++dg) {
                const int dd = dg * 16 + l7 + l16h;
                const uint32_t off =
                    swz((uint32_t)(dd * 128 + kcol * 2)) + nchunk;
                uint32_t B2[4];
                LDSM_X4(B2, XNB + off);
                hmma(accO[2 * dg],     AK, B2);
                hmma(accO[2 * dg + 1], AK, B2 + 2);
            }
        }

        // done reading stage cs
        if (l == 0) MBAR_ARRIVE(mbE + cs * 8);
    }

    // ---- den reduction: shfl across quad lanes, write per n-group ----
    float* sDen = (float*)(smc + SDEN);     // [2][128]
    {
        float v0 = dsum0, v1 = dsum1;
        v0 += __shfl_xor_sync(0xFFFFFFFFu, v0, 1);
        v0 += __shfl_xor_sync(0xFFFFFFFFu, v0, 2);
        v1 += __shfl_xor_sync(0xFFFFFFFFu, v1, 1);
        v1 += __shfl_xor_sync(0xFFFFFFFFu, v1, 2);
        if (lr == 0) {
            sDen[wn * 128 + mA] = v0;
            sDen[wn * 128 + mA + 8] = v1;
        }
    }
    __syncthreads();   // all warps done with all tiles; sDen visible

    // ---- partial-O epilogue: scale by STEP/den, write per n-group region ----
    const int mB2 = mA + 8;
    const float scA = STEP / (sDen[mA] + sDen[128 + mA]);
    const float scB = STEP / (sDen[mB2] + sDen[128 + mB2]);
    float* sO = (float*)(smc + wn * 33792);   // [64 d][132 m]
    #pragma unroll
    for (int dg = 0; dg < 4; ++dg)
        #pragma unroll
        for (int s = 0; s < 2; ++s) {
            const float* c = accO[2 * dg + s];
            const int dbase = dg * 16 + s * 8 + 2 * lr;
            sO[dbase * 132 + mA]        = c[0] * scA;
            sO[(dbase + 1) * 132 + mA]  = c[1] * scA;
            sO[dbase * 132 + mB2]       = c[2] * scB;
            sO[(dbase + 1) * 132 + mB2] = c[3] * scB;
        }
    __syncthreads();

    // ---- combine partials + blend with x, store + next-iter image ----
    unsigned char* phn = g_xh[(it + 1) & 1] + (size_t)(b * NT + blockIdx.x) * IMG;
    const float* sO0 = (const float*)(smc);
    const float* sO1 = (const float*)(smc + 33792);
    float psum[4] = {0.0f, 0.0f, 0.0f, 0.0f};
    #pragma unroll
    for (int q = 0; q < 4; ++q) {
        int task = q * THREADS + tid;       // dd(64) x mq(32)
        int dd = task >> 5, mq = task & 31;
        float4 o0 = *(const float4*)&sO0[dd * 132 + mq * 4];
        float4 o1 = *(const float4*)&sO1[dd * 132 + mq * 4];
        float4 x = *(const float4*)(xin + (size_t)dd * N + m0 + mq * 4);
        float4 r;
        r.x = fmaf(1.0f - STEP, x.x, o0.x + o1.x);
        r.y = fmaf(1.0f - STEP, x.y, o0.y + o1.y);
        r.z = fmaf(1.0f - STEP, x.z, o0.z + o1.z);
        r.w = fmaf(1.0f - STEP, x.w, o0.w + o1.w);
        *(float4*)(xout + (size_t)dd * N + m0 + mq * 4) = r;
        // next-iteration fp16 image (ping-pong buffer)
        uint32_t hp0 = pack_f16(r.y, r.x);
        uint32_t hp1 = pack_f16(r.w, r.z);
        int mit = mq * 4;
        uint32_t off = (mit >> 6) * 8192
                     + swz((uint32_t)(dd * 128 + ((mit & 63) >> 3) * 16))
                     + (mit & 7) * 2;
        *(uint2*)(phn + off) = make_uint2(hp0, hp1);
        psum[0] = fmaf(r.x, r.x, psum[0]);
        psum[1] = fmaf(r.y, r.y, psum[1]);
        psum[2] = fmaf(r.z, r.z, psum[2]);
        psum[3] = fmaf(r.w, r.w, psum[3]);
    }
    __syncthreads();   // sO reads done; reuse region for norm reduction
    float* sP = (float*)smc;               // [16][128]
    {
        int grp = tid >> 5, mq = tid & 31;
        #pragma unroll
        for (int j = 0; j < 4; ++j)
            sP[grp * 128 + mq * 4 + j] = psum[j];
    }
    __syncthreads();
    if (tid < BM) {
        float s = 0.0f;
        #pragma unroll
        for (int g = 0; g < 16; ++g) s += sP[g * 128 + tid];
        g_tsh[(it + 1) & 1][(size_t)b * N + m0 + tid] = fmaf(C, s, 2.0f);
    }
}

extern "C" void kernel_launch(void* const* d_in, const int* in_sizes, int n_in,
                              void* d_out, int out_size) {
    const float* x = (const float*)d_in[0];
    float* out = (float*)d_out;

    cudaFuncSetAttribute(ms_mma_kernel,
                         cudaFuncAttributeMaxDynamicSharedMemorySize, SMEM_BYTES);

    dim3 grid(NT, B);
    init_kernel<<<grid, 256>>>(x, out);
    for (int it = 0; it < ITERS; ++it)
        ms_mma_kernel<<<grid, THREADS, SMEM_BYTES>>>(out, it);
}

// round 15
// speedup vs baseline: 1.0666x; 1.0481x over previous
#include <cuda_runtime.h>
#include <cuda_fp16.h>
#include <cstdint>

// ---------------- problem constants ----------------
constexpr int B = 2;
constexpr int D = 64;
constexpr int N = 96 * 96;      // 9216
constexpr int ITERS = 4;
constexpr float STEP = 0.5f;
constexpr float KBW = 0.3f;
constexpr float LOG2E = 1.4426950408889634f;

constexpr int BM = 128;
constexpr int BN = 128;
constexpr int THREADS = 512;
constexpr int NT = N / BN;      // 72
constexpr int STAGES = 8;

// Tile image: 2 chunks x [64 d][64 pt] fp16, 128B swizzled rows = 16384 B
constexpr int IMG = 16384;

// ping-pong operand buffers (iter parity)
__device__ __align__(16) unsigned char g_xh[2][(size_t)B * NT * IMG];
__device__ float g_tsh[2][(size_t)B * N];

// ---------------- smem layout (bytes) ----------------
constexpr int XM_H = 0;              // 16 KB
constexpr int XN_BASE = 16384;       // STAGES x 16 KB
constexpr int XN_STRIDE = 16384;
constexpr int SDEN = XN_BASE + STAGES * XN_STRIDE;   // 147456; 256 f32
constexpr int MBAR = SDEN + 1024;
constexpr int SMEM_BYTES = MBAR + 256;
// epilogue reuse: sO0 f32[64][132] at 0, sO1 at 33792; then sP f32[16][128] at 0

// ---------------- asm helpers ----------------
__device__ __forceinline__ uint32_t smem_u32(const void* p) {
    uint32_t a;
    asm("{ .reg .u64 t; cvta.to.shared.u64 t, %1; cvt.u32.u64 %0, t; }"
        : "=r"(a) : "l"(p));
    return a;
}

__device__ __forceinline__ uint32_t swz(uint32_t o) {
    return o ^ ((o >> 3) & 0x70);
}

#define MBAR_INIT(mbar, cnt) \
    asm volatile("mbarrier.init.shared.b64 [%0], %1;" :: "r"(mbar), "r"(cnt) : "memory")

#define MBAR_EXPECT_TX(mbar, bytes) \
    asm volatile("mbarrier.arrive.expect_tx.shared.b64 _, [%0], %1;" \
                 :: "r"(mbar), "r"(bytes) : "memory")

#define MBAR_ARRIVE(mbar) \
    asm volatile("mbarrier.arrive.shared.b64 _, [%0];" :: "r"(mbar) : "memory")

#define MBAR_WAIT(mbar, parity) do {                                          \
    uint32_t _m = (mbar), _p = (parity);                                      \
    asm volatile(                                                             \
        "{\n\t.reg .pred P1;\n\t"                                             \
        "WAIT_LOOP_%=:\n\t"                                                   \
        "mbarrier.try_wait.parity.acquire.cta.shared::cta.b64 P1, [%0], %1, 0x989680;\n\t" \
        "@P1 bra.uni WAIT_DONE_%=;\n\t"                                       \
        "bra.uni WAIT_LOOP_%=;\n\t"                                           \
        "WAIT_DONE_%=:\n\t}"                                                  \
        :: "r"(_m), "r"(_p) : "memory");                                      \
} while (0)

__device__ __forceinline__ void bulk_g2s(uint32_t dst, const void* src,
                                         uint32_t bytes, uint32_t mbar) {
    asm volatile(
        "cp.async.bulk.shared::cluster.global.mbarrier::complete_tx::bytes "
        "[%0], [%1], %2, [%3];"
        :: "r"(dst), "l"(__cvta_generic_to_global(src)), "r"(bytes), "r"(mbar)
        : "memory");
}

#define LDSM_X4(r, addr)                                                     \
    asm volatile("ldmatrix.sync.aligned.m8n8.x4.shared.b16 {%0,%1,%2,%3}, [%4];" \
        : "=r"((r)[0]), "=r"((r)[1]), "=r"((r)[2]), "=r"((r)[3]) : "r"(addr))

#define LDSM_X4_T(r, addr)                                                   \
    asm volatile("ldmatrix.sync.aligned.m8n8.x4.trans.shared.b16 {%0,%1,%2,%3}, [%4];" \
        : "=r"((r)[0]), "=r"((r)[1]), "=r"((r)[2]), "=r"((r)[3]) : "r"(addr))

__device__ __forceinline__ void hmma(float* c, const uint32_t* a, const uint32_t* b) {
    asm volatile(
        "mma.sync.aligned.m16n8k16.row.col.f32.f16.f16.f32 "
        "{%0,%1,%2,%3}, {%4,%5,%6,%7}, {%8,%9}, {%0,%1,%2,%3};"
        : "+f"(c[0]), "+f"(c[1]), "+f"(c[2]), "+f"(c[3])
        : "r"(a[0]), "r"(a[1]), "r"(a[2]), "r"(a[3]), "r"(b[0]), "r"(b[1]));
}

// pack two f32 into f16x2 (lo = second arg), saturating to finite
__device__ __forceinline__ uint32_t pack_f16(float hi, float lo) {
    uint32_t r;
    asm("cvt.rn.satfinite.f16x2.f32 %0, %1, %2;" : "=r"(r) : "f"(hi), "f"(lo));
    return r;
}

// 2^t via MUFU (otherwise-idle pipe; ~2 ulp)
__device__ __forceinline__ float ex2a(float t) {
    float r;
    asm("ex2.approx.f32 %0, %1;" : "=f"(r) : "f"(t));
    return r;
}

// init: copy x0 into out slice 0, build fp16 image buf0 + tsh buf0
__global__ __launch_bounds__(256)
void init_kernel(const float* __restrict__ x, float* __restrict__ out) {
    const int t = blockIdx.x, b = blockIdx.y;
    const int tid = threadIdx.x;
    const float* xs = x + (size_t)b * D * N;
    float* os = out + (size_t)b * (ITERS + 1) * D * N;
    unsigned char* ph = g_xh[0] + (size_t)(b * NT + t) * IMG;
    #pragma unroll
    for (int q = 0; q < 4; ++q) {
        int task = q * 256 + tid;          // c(2) x d(64) x g(8)
        int c = task >> 9, rem = task & 511;
        int d = rem >> 3, g = rem & 7;
        int n0 = t * BN + c * 64 + g * 8;
        const float4* s = (const float4*)(xs + (size_t)d * N + n0);
        float4 v0 = s[0], v1 = s[1];
        float4* o = (float4*)(os + (size_t)d * N + n0);
        o[0] = v0;
        o[1] = v1;
        uint32_t hp[4];
        hp[0] = pack_f16(v0.y, v0.x);
        hp[1] = pack_f16(v0.w, v0.z);
        hp[2] = pack_f16(v1.y, v1.x);
        hp[3] = pack_f16(v1.w, v1.z);
        uint32_t off = c * 8192 + swz((uint32_t)(d * 128 + g * 16));
        *(uint4*)(ph + off) = make_uint4(hp[0], hp[1], hp[2], hp[3]);
    }
    if (tid < BN) {
        int n = t * BN + tid;
        float s = 0.0f;
        #pragma unroll 8
        for (int d = 0; d < D; ++d) {
            float v = xs[(size_t)d * N + n];
            s = fmaf(v, v, s);
        }
        g_tsh[0][(size_t)b * N + n] = fmaf(KBW * LOG2E, s, 2.0f);
    }
}

// ---------------- main kernel ----------------
__global__ __launch_bounds__(THREADS, 1)
void ms_mma_kernel(float* __restrict__ out, int it) {
    extern __shared__ unsigned char smc[];
    uint32_t sb = smem_u32(smc);

    const int tid = threadIdx.x;
    const int l = tid & 31;
    const int w = tid >> 5;
    const int wm = w >> 1;       // 8 m-groups of 16 rows
    const int wn = w & 1;        // 2 n-groups of 64 cols

    const int b = blockIdx.y;
    const int m0 = blockIdx.x * BM;
    const float* __restrict__ xin = out + ((size_t)b * (ITERS + 1) + it) * (size_t)(D * N);
    float* __restrict__ xout = (float*)xin + (size_t)D * N;

    const int l7 = l & 7, l8 = l & 8, l16h = (l & 16) >> 1, lq = l >> 2, lr = l & 3;

    const uint32_t mbF = sb + MBAR;            // full[8]
    const uint32_t mbE = sb + MBAR + 64;       // empty[8]
    const uint32_t mbx = sb + MBAR + 128;

    // ---- prologue ----
    if (tid == 0) {
        #pragma unroll
        for (int s = 0; s < STAGES; ++s) {
            MBAR_INIT(mbF + s * 8, 1);
            MBAR_INIT(mbE + s * 8, 16);
        }
        MBAR_INIT(mbx, 1);
    }
    __syncthreads();
    const unsigned char* gh = g_xh[it & 1] + (size_t)b * NT * IMG;
    if (tid == 0) {
        MBAR_EXPECT_TX(mbx, IMG);
        bulk_g2s(sb + XM_H, gh + (size_t)blockIdx.x * IMG, IMG, mbx);
        #pragma unroll
        for (int u = 0; u < 6; ++u) {
            MBAR_EXPECT_TX(mbF + u * 8, IMG);
            bulk_g2s(sb + XN_BASE + u * XN_STRIDE, gh + (size_t)u * IMG, IMG, mbF + u * 8);
        }
    }

    // per-warp address components
    const int mchunk = (wm >> 2) * 8192;
    const int mcol = (wm & 3) * 16 + l8;
    const int nchunk = wn * 8192;

    // per-thread K-column shifts (rows mA, mA+8)
    const int mA = wm * 16 + lq;
    const float ntsA = -g_tsh[it & 1][(size_t)b * N + m0 + mA];
    const float ntsB = -g_tsh[it & 1][(size_t)b * N + m0 + mA + 8];
    const float C = KBW * LOG2E;

    const uint32_t oneh = 0x3C003C00u;   // fp16 {1,1}
    const uint32_t bOne[2] = {oneh, oneh};

    float accO[8][4];
    #pragma unroll
    for (int j = 0; j < 8; ++j)
        #pragma unroll
        for (int c = 0; c < 4; ++c) accO[j][c] = 0.0f;
    float accD[4] = {0.0f, 0.0f, 0.0f, 0.0f};

    // ---- hoist Xmh A-fragments (loop-invariant, 16 regs) ----
    MBAR_WAIT(mbx, 0);
    uint32_t Ah[4][4];
    #pragma unroll
    for (int k = 0; k < 4; ++k) {
        const uint32_t offA =
            swz((uint32_t)((k * 16 + l7 + l16h) * 128 + mcol * 2)) + mchunk;
        LDSM_X4_T(Ah[k], sb + XM_H + offA);
    }

    for (int t = 0; t < NT; ++t) {
        // producer: prefetch tile t+6 into stage (t+6)%STAGES
        if (tid == 0) {
            const int u = t + 6;
            if (u < NT) {
                const int us = u & 7, uj = u >> 3;
                if (u >= STAGES) MBAR_WAIT(mbE + us * 8, (uj - 1) & 1);
                MBAR_EXPECT_TX(mbF + us * 8, IMG);
                bulk_g2s(sb + XN_BASE + us * XN_STRIDE, gh + (size_t)u * IMG,
                         IMG, mbF + us * 8);
            }
        }
        const int cs = t & 7;
        const uint32_t XNB = sb + XN_BASE + cs * XN_STRIDE;
        MBAR_WAIT(mbF + cs * 8, (t >> 3) & 1);

        // ---- software-pipelined np loop: S(np+1) issued before exp/MMA2(np) ----
        float sc0[4], sc1[4], sn0[4], sn1[4];
        // prologue: S(0)
        #pragma unroll
        for (int c = 0; c < 4; ++c) { sc0[c] = 0.0f; sc1[c] = 0.0f; }
        #pragma unroll
        for (int k = 0; k < 4; ++k) {
            uint32_t Bh[4];
            const uint32_t offB =
                swz((uint32_t)((k * 16 + l7 + l8) * 128 + l16h * 2)) + nchunk;
            LDSM_X4_T(Bh, XNB + offB);
            hmma(sc0, Ah[k], Bh);
            hmma(sc1, Ah[k], Bh + 2);
        }
        #pragma unroll
        for (int np = 0; np < 4; ++np) {
            // issue S(np+1) first: gives S(np) results slack before exp reads them
            if (np < 3) {
                #pragma unroll
                for (int c = 0; c < 4; ++c) { sn0[c] = 0.0f; sn1[c] = 0.0f; }
                #pragma unroll
                for (int k = 0; k < 4; ++k) {
                    uint32_t Bh[4];
                    const uint32_t offB =
                        swz((uint32_t)((k * 16 + l7 + l8) * 128
                                       + ((np + 1) * 16 + l16h) * 2)) + nchunk;
                    LDSM_X4_T(Bh, XNB + offB);
                    hmma(sn0, Ah[k], Bh);
                    hmma(sn1, Ah[k], Bh + 2);
                }
            }
            // K' = 2^(C*S - tsh) via MUFU -> fp16 A fragment
            uint32_t AK[4];
            AK[0] = pack_f16(ex2a(fmaf(sc0[1], C, ntsA)), ex2a(fmaf(sc0[0], C, ntsA)));
            AK[1] = pack_f16(ex2a(fmaf(sc0[3], C, ntsB)), ex2a(fmaf(sc0[2], C, ntsB)));
            AK[2] = pack_f16(ex2a(fmaf(sc1[1], C, ntsA)), ex2a(fmaf(sc1[0], C, ntsA)));
            AK[3] = pack_f16(ex2a(fmaf(sc1[3], C, ntsB)), ex2a(fmaf(sc1[2], C, ntsB)));
            hmma(accD, AK, bOne);
            const int kcol = np * 16 + l8;
            #pragma unroll
            for (int dg = 0; dg < 4; ++dg) {
                const int dd = dg * 16 + l7 + l16h;
                const uint32_t off =
                    swz((uint32_t)(dd * 128 + kcol * 2)) + nchunk;
                uint32_t B2[4];
                LDSM_X4(B2, XNB + off);
                hmma(accO[2 * dg],     AK, B2);
                hmma(accO[2 * dg + 1], AK, B2 + 2);
            }
            // rotate S buffers
            #pragma unroll
            for (int c = 0; c < 4; ++c) { sc0[c] = sn0[c]; sc1[c] = sn1[c]; }
        }

        // done reading stage cs
        if (l == 0) MBAR_ARRIVE(mbE + cs * 8);
    }

    // ---- den: accD[0]=rows lq, accD[2]=rows lq+8 (all quad lanes equal) ----
    float* sDen = (float*)(smc + SDEN);     // [2][128]
    if (lr == 0) {
        sDen[wn * 128 + mA] = accD[0];
        sDen[wn * 128 + mA + 8] = accD[2];
    }
    __syncthreads();   // all warps done with all tiles; sDen visible

    // ---- partial-O epilogue: scale by STEP/den, write per n-group region ----
    const int mB2 = mA + 8;
    const float scA = STEP / (sDen[mA] + sDen[128 + mA]);
    const float scB = STEP / (sDen[mB2] + sDen[128 + mB2]);
    float* sO = (float*)(smc + wn * 33792);   // [64 d][132 m]
    #pragma unroll
    for (int dg = 0; dg < 4; ++dg)
        #pragma unroll
        for (int s = 0; s < 2; ++s) {
            const float* c = accO[2 * dg + s];
            const int dbase = dg * 16 + s * 8 + 2 * lr;
            sO[dbase * 132 + mA]        = c[0] * scA;
            sO[(dbase + 1) * 132 + mA]  = c[1] * scA;
            sO[dbase * 132 + mB2]       = c[2] * scB;
            sO[(dbase + 1) * 132 + mB2] = c[3] * scB;
        }
    __syncthreads();

    // ---- combine partials + blend with x, store + next-iter image ----
    unsigned char* phn = g_xh[(it + 1) & 1] + (size_t)(b * NT + blockIdx.x) * IMG;
    const float* sO0 = (const float*)(smc);
    const float* sO1 = (const float*)(smc + 33792);
    float psum[4] = {0.0f, 0.0f, 0.0f, 0.0f};
    #pragma unroll
    for (int q = 0; q < 4; ++q) {
        int task = q * THREADS + tid;       // dd(64) x mq(32)
        int dd = task >> 5, mq = task & 31;
        float4 o0 = *(const float4*)&sO0[dd * 132 + mq * 4];
        float4 o1 = *(const float4*)&sO1[dd * 132 + mq * 4];
        float4 x = *(const float4*)(xin + (size_t)dd * N + m0 + mq * 4);
        float4 r;
        r.x = fmaf(1.0f - STEP, x.x, o0.x + o1.x);
        r.y = fmaf(1.0f - STEP, x.y, o0.y + o1.y);
        r.z = fmaf(1.0f - STEP, x.z, o0.z + o1.z);
        r.w = fmaf(1.0f - STEP, x.w, o0.w + o1.w);
        *(float4*)(xout + (size_t)dd * N + m0 + mq * 4) = r;
        // next-iteration fp16 image (ping-pong buffer)
        uint32_t hp0 = pack_f16(r.y, r.x);
        uint32_t hp1 = pack_f16(r.w, r.z);
        int mit = mq * 4;
        uint32_t off = (mit >> 6) * 8192
                     + swz((uint32_t)(dd * 128 + ((mit & 63) >> 3) * 16))
                     + (mit & 7) * 2;
        *(uint2*)(phn + off) = make_uint2(hp0, hp1);
        psum[0] = fmaf(r.x, r.x, psum[0]);
        psum[1] = fmaf(r.y, r.y, psum[1]);
        psum[2] = fmaf(r.z, r.z, psum[2]);
        psum[3] = fmaf(r.w, r.w, psum[3]);
    }
    __syncthreads();   // sO reads done; reuse region for norm reduction
    float* sP = (float*)smc;               // [16][128]
    {
        int grp = tid >> 5, mq = tid & 31;
        #pragma unroll
        for (int j = 0; j < 4; ++j)
            sP[grp * 128 + mq * 4 + j] = psum[j];
    }
    __syncthreads();
    if (tid < BM) {
        float s = 0.0f;
        #pragma unroll
        for (int g = 0; g < 16; ++g) s += sP[g * 128 + tid];
        g_tsh[(it + 1) & 1][(size_t)b * N + m0 + tid] = fmaf(C, s, 2.0f);
    }
}

extern "C" void kernel_launch(void* const* d_in, const int* in_sizes, int n_in,
                              void* d_out, int out_size) {
    const float* x = (const float*)d_in[0];
    float* out = (float*)d_out;

    cudaFuncSetAttribute(ms_mma_kernel,
                         cudaFuncAttributeMaxDynamicSharedMemorySize, SMEM_BYTES);

    dim3 grid(NT, B);
    init_kernel<<<grid, 256>>>(x, out);
    for (int it = 0; it < ITERS; ++it)
        ms_mma_kernel<<<grid, THREADS, SMEM_BYTES>>>(out, it);
}